// round 11
// baseline (speedup 1.0000x reference)
#include <cuda_runtime.h>
#include <cuda_bf16.h>

// Problem shape (fixed by the dataset): B=16, N=2048, NUM_BUCKETS=128
#define BB      16
#define NN      2048
#define NBUCK   128
#define THREADS 256
#define RPB     8                 // rows per block, i-stride 4 (same i mod 4)
#define VPT     2                 // float4 chunks per thread per row: 2048/(256*4)

// out[b,i,j] = pos_w[N-1 + j - i] + ts_w[bucket(b,i,j)]
// bucket = trunc( logf(max(|td|,1)) / 0.301f ), td = ts[min(i+1,N-1)] - ts[j] (j<=i), else 0.
// td < 1e7 -> max bucket 53. Integer form: bucket(d) = #{k>=1 : T_k <= d},
// T_k = min{d : logf((float)d)/0.301f >= k}; <=3 thresholds per octave ->
// bucket(d) = lut[e].base + (d>=t1)+(d>=t2)+(d>=t3), e = ilog2(d).
// ts sorted ascending => d = tsn_r - ts[j] is non-increasing in j, non-decreasing in r.
// => the 32-elem (4j x 8row) tile's buckets are bracketed by bucket(dmin), bucket(dmax):
//    equal => ONE ts_w value for the whole tile (hot path, no per-row bucket work).
__global__ __launch_bounds__(THREADS)
void bias_kernel(const int*   __restrict__ ts,      // int32 [B,N]
                 const float* __restrict__ ts_w,    // [129]
                 const float* __restrict__ pos_w,   // [2N-1]
                 float*       __restrict__ out)     // [B,N,N] fp32
{
    __shared__ __align__(16) float s_pos[2080];  // pos window for this block's 8 rows
    __shared__ int   s_T[64];                    // thresholds T_1..T_53
    __shared__ int4  s_lut[24];                  // per-exponent {base, t1, t2, t3}
    __shared__ float s_tsw[NBUCK + 1];
    __shared__ int   s_tsn[RPB];

    const int t   = threadIdx.x;
    const int blk = blockIdx.x;                  // 0..255
    const int b   = blockIdx.y;
    // Rows: base + 4r, r=0..7.  base mod 4 constant within block.
    const int base = (blk & 3) + (blk >> 2) * 32;
    const int o7   = 2047 - base - 28;           // pos_w offset of staged window start
    const int* tsrow = ts + (size_t)b * NN;

    // ---- stage pos window (2076 floats), coalesced ----
    #pragma unroll
    for (int x = t; x < 2076; x += THREADS)
        s_pos[x] = pos_w[o7 + x];

    // ---- thresholds: exact match of precise logf(x)/0.301f bucketization ----
    if (t <= 53) {
        if (t == 0) {
            s_T[0] = 1;
        } else {
            const float k = (float)t;
            int d = (int)ceilf(expf(0.301f * k));
            if (d < 2) d = 2;
            #pragma unroll 1
            while (d > 2 && (logf((float)(d - 1)) / 0.301f) >= k) d--;
            #pragma unroll 1
            while ((logf((float)d) / 0.301f) < k) d++;
            s_T[t] = d;
        }
    }
    if (t <= NBUCK) s_tsw[t] = ts_w[t];
    if (t < RPB) {
        int i = base + 4 * t;
        s_tsn[t] = tsrow[(i < NN - 1) ? (i + 1) : (NN - 1)];
    }

    // Register-cache this thread's 8 timestamps as int4 (4 consecutive j per chunk).
    int4 tsd[VPT];
    const int4* tsrow4 = (const int4*)tsrow;
    #pragma unroll
    for (int v = 0; v < VPT; v++)
        tsd[v] = tsrow4[t + v * THREADS];

    __syncthreads();

    if (t < 24) {
        const int lo = 1 << t;
        int cnt = 0;
        #pragma unroll
        for (int k = 1; k <= 53; k++) cnt += (s_T[k] <= lo) ? 1 : 0;
        int4 q;
        q.x = cnt;
        q.y = (cnt + 1 <= 53) ? s_T[cnt + 1] : 0x7FFFFFFF;
        q.z = (cnt + 2 <= 53) ? s_T[cnt + 2] : 0x7FFFFFFF;
        q.w = (cnt + 3 <= 53) ? s_T[cnt + 3] : 0x7FFFFFFF;
        s_lut[t] = q;
    }
    __syncthreads();

    const float tw0  = s_tsw[0];
    const int   tsn0 = s_tsn[0];
    const int   tsn7 = s_tsn[RPB - 1];

    #pragma unroll
    for (int v = 0; v < VPT; v++) {
        const int j0 = 4 * (t + v * THREADS);        // warp: 128 consecutive j

        // ---- tile-level classification (once per 32 output elements) ----
        bool  uniform;
        float w = tw0;
        if (j0 > base + 28) {
            // strictly upper for all 8 rows: bucket 0
            uniform = true;
        } else if (j0 <= base) {
            // bucket path valid for all rows (j>i inside chunk => d<=0 => bucket 0, correct)
            const int dmax = max(tsn7 - tsd[v].x, 1);   // r=7, smallest ts
            const int dmin = max(tsn0 - tsd[v].w, 1);   // r=0, largest ts
            const int4 qx = s_lut[31 - __clz(dmax)];
            const int4 qn = s_lut[31 - __clz(dmin)];
            const int bx = qx.x + (dmax >= qx.y) + (dmax >= qx.z) + (dmax >= qx.w);
            const int bn = qn.x + (dmin >= qn.y) + (dmin >= qn.z) + (dmin >= qn.w);
            uniform = (bx == bn);
            w = s_tsw[bx];
        } else {
            uniform = false;
        }

        if (uniform) {
            // ---- hot path: one weight for the whole 4j x 8row tile ----
            #pragma unroll
            for (int r = 0; r < RPB; r++) {
                const int i = base + 4 * r;
                const float4 p = *(const float4*)&s_pos[(28 - 4 * r) + j0];
                float* outrow = out + ((size_t)b * NN + i) * (size_t)NN;
                float4 rv;
                rv.x = p.x + w;
                rv.y = p.y + w;
                rv.z = p.z + w;
                rv.w = p.w + w;
                *(float4*)(outrow + j0) = rv;        // coalesced STG.128
            }
        } else {
            // ---- fallback: per-row generic (R10 body), ~2% of tiles ----
            #pragma unroll
            for (int r = 0; r < RPB; r++) {
                const int i   = base + 4 * r;
                const int tsn = s_tsn[r];
                const float4 p = *(const float4*)&s_pos[(28 - 4 * r) + j0];
                float* outrow = out + ((size_t)b * NN + i) * (size_t)NN;

                float4 rv;
                if (j0 > i) {
                    rv.x = p.x + tw0;
                    rv.y = p.y + tw0;
                    rv.z = p.z + tw0;
                    rv.w = p.w + tw0;
                } else {
                    const int d0 = max(tsn - tsd[v].x, 1);
                    const int d3 = max(tsn - tsd[v].w, 1);
                    const int4 q0 = s_lut[31 - __clz(d0)];
                    const int4 q3 = s_lut[31 - __clz(d3)];
                    const int b0 = q0.x + (d0 >= q0.y) + (d0 >= q0.z) + (d0 >= q0.w);
                    const int b3 = q3.x + (d3 >= q3.y) + (d3 >= q3.z) + (d3 >= q3.w);
                    if (b0 == b3) {
                        const float wr = s_tsw[b0];
                        rv.x = p.x + wr;
                        rv.y = p.y + wr;
                        rv.z = p.z + wr;
                        rv.w = p.w + wr;
                    } else {
                        const int d1 = max(tsn - tsd[v].y, 1);
                        const int d2 = max(tsn - tsd[v].z, 1);
                        const int4 q1 = s_lut[31 - __clz(d1)];
                        const int4 q2 = s_lut[31 - __clz(d2)];
                        const int b1 = q1.x + (d1 >= q1.y) + (d1 >= q1.z) + (d1 >= q1.w);
                        const int b2 = q2.x + (d2 >= q2.y) + (d2 >= q2.z) + (d2 >= q2.w);
                        rv.x = p.x + s_tsw[b0];
                        rv.y = p.y + s_tsw[b1];
                        rv.z = p.z + s_tsw[b2];
                        rv.w = p.w + s_tsw[b3];
                    }
                }
                *(float4*)(outrow + j0) = rv;
            }
        }
    }
}

extern "C" void kernel_launch(void* const* d_in, const int* in_sizes, int n_in,
                              void* d_out, int out_size)
{
    const int*   ts    = (const int*)d_in[0];    // int32 [16,2048]
    const float* ts_w  = (const float*)d_in[1];  // [129]
    const float* pos_w = (const float*)d_in[2];  // [4095]
    float*       out   = (float*)d_out;          // [16,2048,2048] fp32

    dim3 grid(NN / RPB, BB);
    bias_kernel<<<grid, THREADS>>>(ts, ts_w, pos_w, out);
}

// round 12
// speedup vs baseline: 1.0661x; 1.0661x over previous
#include <cuda_runtime.h>
#include <cuda_bf16.h>

// Problem shape (fixed by the dataset): B=16, N=2048, NUM_BUCKETS=128
#define BB      16
#define NN      2048
#define NBUCK   128
#define THREADS 256
#define RPB     8                 // rows per block, i-stride 4 (same i mod 4)
#define VPT     2                 // float4 chunks per thread per row: 2048/(256*4)

// out[b,i,j] = pos_w[N-1 + j - i] + ts_w[bucket(b,i,j)]
// bucket = trunc( logf(max(|td|,1)) / 0.301f ), td = ts[min(i+1,N-1)] - ts[j] (j<=i), else 0.
// td < 1e7 -> max bucket 53. Integer form: bucket(d) = #{k>=1 : T_k <= d},
// T_k = min{d : logf((float)d)/0.301f >= k}; <=3 thresholds per octave ->
// bucket(d) = lut[e].base + (d>=t1)+(d>=t2)+(d>=t3), e = ilog2(d).
// ts sorted ascending => d = tsn_r - ts[j] non-increasing in j, non-decreasing in r,
// so the 32-elem (4j x 8row) tile's buckets are bracketed by bucket(dmin)/bucket(dmax):
// equal => ONE ts_w value for the whole tile (hot path, no per-row bucket work).
// R11 lesson: hoist helped issue (71->52%) but duplicated unrolled bodies blew regs
// (39->62) and occupancy (60->37%). Fix: launch_bounds cap + rolled fallback loop.
__global__ __launch_bounds__(THREADS, 6)   // cap ~42 regs -> >=1536 threads/SM
void bias_kernel(const int*   __restrict__ ts,      // int32 [B,N]
                 const float* __restrict__ ts_w,    // [129]
                 const float* __restrict__ pos_w,   // [2N-1]
                 float*       __restrict__ out)     // [B,N,N] fp32
{
    __shared__ __align__(16) float s_pos[2080];  // pos window for this block's 8 rows
    __shared__ int   s_T[64];                    // thresholds T_1..T_53
    __shared__ int4  s_lut[24];                  // per-exponent {base, t1, t2, t3}
    __shared__ float s_tsw[NBUCK + 1];
    __shared__ int   s_tsn[RPB];

    const int t   = threadIdx.x;
    const int blk = blockIdx.x;                  // 0..255
    const int b   = blockIdx.y;
    // Rows: base + 4r, r=0..7.  base mod 4 constant within block.
    const int base = (blk & 3) + (blk >> 2) * 32;
    const int o7   = 2047 - base - 28;           // pos_w offset of staged window start
    const int* tsrow = ts + (size_t)b * NN;

    // ---- stage pos window (2076 floats), coalesced ----
    #pragma unroll
    for (int x = t; x < 2076; x += THREADS)
        s_pos[x] = pos_w[o7 + x];

    // ---- thresholds: exact match of precise logf(x)/0.301f bucketization ----
    if (t <= 53) {
        if (t == 0) {
            s_T[0] = 1;
        } else {
            const float k = (float)t;
            int d = (int)ceilf(expf(0.301f * k));
            if (d < 2) d = 2;
            #pragma unroll 1
            while (d > 2 && (logf((float)(d - 1)) / 0.301f) >= k) d--;
            #pragma unroll 1
            while ((logf((float)d) / 0.301f) < k) d++;
            s_T[t] = d;
        }
    }
    if (t <= NBUCK) s_tsw[t] = ts_w[t];
    if (t < RPB) {
        int i = base + 4 * t;
        s_tsn[t] = tsrow[(i < NN - 1) ? (i + 1) : (NN - 1)];
    }

    // Register-cache this thread's 8 timestamps as int4 (4 consecutive j per chunk).
    int4 tsd[VPT];
    const int4* tsrow4 = (const int4*)tsrow;
    #pragma unroll
    for (int v = 0; v < VPT; v++)
        tsd[v] = tsrow4[t + v * THREADS];

    __syncthreads();

    if (t < 24) {
        const int lo = 1 << t;
        int cnt = 0;
        #pragma unroll
        for (int k = 1; k <= 53; k++) cnt += (s_T[k] <= lo) ? 1 : 0;
        int4 q;
        q.x = cnt;
        q.y = (cnt + 1 <= 53) ? s_T[cnt + 1] : 0x7FFFFFFF;
        q.z = (cnt + 2 <= 53) ? s_T[cnt + 2] : 0x7FFFFFFF;
        q.w = (cnt + 3 <= 53) ? s_T[cnt + 3] : 0x7FFFFFFF;
        s_lut[t] = q;
    }
    __syncthreads();

    const float tw0  = s_tsw[0];
    const int   tsn0 = s_tsn[0];
    const int   tsn7 = s_tsn[RPB - 1];
    // Row 0 output pointer for this block; row stride = 4 rows = 4*NN floats.
    float* out0 = out + ((size_t)b * NN + base) * (size_t)NN;

    #pragma unroll
    for (int v = 0; v < VPT; v++) {
        const int j0 = 4 * (t + v * THREADS);        // warp: 128 consecutive j

        // ---- tile-level classification (once per 32 output elements) ----
        bool  uniform;
        float w = tw0;
        if (j0 > base + 28) {
            // strictly upper for all 8 rows: bucket 0
            uniform = true;
        } else if (j0 <= base) {
            // bucket path valid for all rows (j>i inside chunk => d<=0 => bucket 0, OK)
            const int dmax = max(tsn7 - tsd[v].x, 1);   // r=7, smallest ts[j]
            const int dmin = max(tsn0 - tsd[v].w, 1);   // r=0, largest ts[j]
            const int4 qx = s_lut[31 - __clz(dmax)];
            const int4 qn = s_lut[31 - __clz(dmin)];
            const int bx = qx.x + (dmax >= qx.y) + (dmax >= qx.z) + (dmax >= qx.w);
            const int bn = qn.x + (dmin >= qn.y) + (dmin >= qn.z) + (dmin >= qn.w);
            uniform = (bx == bn);
            w = s_tsw[bx];
        } else {
            uniform = false;
        }

        if (uniform) {
            // ---- hot path: one weight for the whole 4j x 8row tile ----
            float* op = out0 + j0;
            const float* pp = &s_pos[28 + j0];
            #pragma unroll
            for (int r = 0; r < RPB; r++) {
                const float4 p = *(const float4*)(pp - 4 * r);
                float4 rv;
                rv.x = p.x + w;
                rv.y = p.y + w;
                rv.z = p.z + w;
                rv.w = p.w + w;
                *(float4*)op = rv;                   // coalesced STG.128
                op += 4 * NN;
            }
        } else {
            // ---- fallback: per-row generic, rare (~2% of tiles). Rolled to keep
            // register pressure and I-stream small; hot path owns the budget. ----
            float* op = out0 + j0;
            #pragma unroll 1
            for (int r = 0; r < RPB; r++) {
                const int i   = base + 4 * r;
                const int tsn = s_tsn[r];
                const float4 p = *(const float4*)&s_pos[(28 - 4 * r) + j0];

                float4 rv;
                if (j0 > i) {
                    rv.x = p.x + tw0;
                    rv.y = p.y + tw0;
                    rv.z = p.z + tw0;
                    rv.w = p.w + tw0;
                } else {
                    const int d0 = max(tsn - tsd[v].x, 1);
                    const int d1 = max(tsn - tsd[v].y, 1);
                    const int d2 = max(tsn - tsd[v].z, 1);
                    const int d3 = max(tsn - tsd[v].w, 1);
                    const int4 q0 = s_lut[31 - __clz(d0)];
                    const int4 q1 = s_lut[31 - __clz(d1)];
                    const int4 q2 = s_lut[31 - __clz(d2)];
                    const int4 q3 = s_lut[31 - __clz(d3)];
                    const int b0 = q0.x + (d0 >= q0.y) + (d0 >= q0.z) + (d0 >= q0.w);
                    const int b1 = q1.x + (d1 >= q1.y) + (d1 >= q1.z) + (d1 >= q1.w);
                    const int b2 = q2.x + (d2 >= q2.y) + (d2 >= q2.z) + (d2 >= q2.w);
                    const int b3 = q3.x + (d3 >= q3.y) + (d3 >= q3.z) + (d3 >= q3.w);
                    rv.x = p.x + s_tsw[b0];
                    rv.y = p.y + s_tsw[b1];
                    rv.z = p.z + s_tsw[b2];
                    rv.w = p.w + s_tsw[b3];
                }
                *(float4*)op = rv;
                op += 4 * NN;
            }
        }
    }
}

extern "C" void kernel_launch(void* const* d_in, const int* in_sizes, int n_in,
                              void* d_out, int out_size)
{
    const int*   ts    = (const int*)d_in[0];    // int32 [16,2048]
    const float* ts_w  = (const float*)d_in[1];  // [129]
    const float* pos_w = (const float*)d_in[2];  // [4095]
    float*       out   = (float*)d_out;          // [16,2048,2048] fp32

    dim3 grid(NN / RPB, BB);
    bias_kernel<<<grid, THREADS>>>(ts, ts_w, pos_w, out);
}

// round 13
// speedup vs baseline: 1.2044x; 1.1298x over previous
#include <cuda_runtime.h>
#include <cuda_bf16.h>

// Problem shape (fixed by the dataset): B=16, N=2048, NUM_BUCKETS=128
#define BB      16
#define NN      2048
#define NBUCK   128
#define THREADS 256
#define RPB     8                 // rows per block, i-stride 4 (same i mod 4)
#define VPT     2                 // float4 chunks per thread per row: 2048/(256*4)

// out[b,i,j] = pos_w[N-1 + j - i] + ts_w[bucket(b,i,j)]
// bucket = trunc( logf(max(|td|,1)) / 0.301f ), td = ts[min(i+1,N-1)] - ts[j] (j<=i), else 0.
// td < 1e7 -> max bucket 53. Integer form: bucket(d) = #{k>=1 : T_k <= d},
// T_k = min{d : logf((float)d)/0.301f >= k}; <=3 thresholds per octave ->
// bucket(d) = lut[e].base + (d>=t1)+(d>=t2)+(d>=t3), e = ilog2(d).
// ts sorted => within a 4-chunk d0>=d3, so bucket uniform over the chunk iff
// d3 >= T_{b0} (single threshold test instead of a second full bucket compute).
// R11/R12 lesson: tile-level (8-row) hoisting loses to this interleaved form
// (divergence + low-ILP store chains); R10 architecture restored here.
__global__ __launch_bounds__(THREADS)
void bias_kernel(const int*   __restrict__ ts,      // int32 [B,N]
                 const float* __restrict__ ts_w,    // [129]
                 const float* __restrict__ pos_w,   // [2N-1]
                 float*       __restrict__ out)     // [B,N,N] fp32
{
    __shared__ __align__(16) float s_pos[2080];  // pos window for this block's 8 rows
    __shared__ int   s_T[64];                    // thresholds: T_0=1, T_1..T_53
    __shared__ int4  s_lut[24];                  // per-exponent {base, t1, t2, t3}
    __shared__ float s_tsw[NBUCK + 1];
    __shared__ int   s_tsn[RPB];

    const int t   = threadIdx.x;
    const int blk = blockIdx.x;                  // 0..255
    const int b   = blockIdx.y;
    // Rows: base + 4r, r=0..7.  base mod 4 constant within block.
    const int base = (blk & 3) + (blk >> 2) * 32;
    const int o7   = 2047 - base - 28;           // pos_w offset of staged window start
    const int* tsrow = ts + (size_t)b * NN;

    // ---- stage pos window (2076 floats), coalesced ----
    #pragma unroll
    for (int x = t; x < 2076; x += THREADS)
        s_pos[x] = pos_w[o7 + x];

    // ---- thresholds: exact match of precise logf(x)/0.301f bucketization ----
    if (t <= 53) {
        if (t == 0) {
            s_T[0] = 1;
        } else {
            const float k = (float)t;
            int d = (int)ceilf(expf(0.301f * k));
            if (d < 2) d = 2;
            #pragma unroll 1
            while (d > 2 && (logf((float)(d - 1)) / 0.301f) >= k) d--;
            #pragma unroll 1
            while ((logf((float)d) / 0.301f) < k) d++;
            s_T[t] = d;
        }
    }
    if (t >= 54 && t < 64) s_T[t] = 0x7FFFFFFF;  // sentinel for T_{b0+?} reads
    if (t <= NBUCK) s_tsw[t] = ts_w[t];
    if (t < RPB) {
        int i = base + 4 * t;
        s_tsn[t] = tsrow[(i < NN - 1) ? (i + 1) : (NN - 1)];
    }

    // Register-cache this thread's 8 timestamps as int4 (4 consecutive j per chunk).
    int4 tsd[VPT];
    const int4* tsrow4 = (const int4*)tsrow;
    #pragma unroll
    for (int v = 0; v < VPT; v++)
        tsd[v] = tsrow4[t + v * THREADS];

    __syncthreads();

    if (t < 24) {
        const int lo = 1 << t;
        int cnt = 0;
        #pragma unroll
        for (int k = 1; k <= 53; k++) cnt += (s_T[k] <= lo) ? 1 : 0;
        int4 q;
        q.x = cnt;
        q.y = (cnt + 1 <= 53) ? s_T[cnt + 1] : 0x7FFFFFFF;
        q.z = (cnt + 2 <= 53) ? s_T[cnt + 2] : 0x7FFFFFFF;
        q.w = (cnt + 3 <= 53) ? s_T[cnt + 3] : 0x7FFFFFFF;
        s_lut[t] = q;
    }
    __syncthreads();

    const float tw0 = s_tsw[0];

    #pragma unroll
    for (int r = 0; r < RPB; r++) {
        const int i     = base + 4 * r;
        const int tsn   = s_tsn[r];
        const int pbase = 28 - 4 * r;            // (2047-i) - o7, multiple of 4
        float* outrow = out + ((size_t)b * NN + i) * (size_t)NN;

        #pragma unroll
        for (int v = 0; v < VPT; v++) {
            const int j0 = 4 * (t + v * THREADS);    // warp: 128 consecutive j
            const float4 p = *(const float4*)&s_pos[pbase + j0];  // aligned LDS.128

            float4 rv;
            if (j0 > i) {
                // strictly upper triangle: bucket 0
                rv.x = p.x + tw0;
                rv.y = p.y + tw0;
                rv.z = p.z + tw0;
                rv.w = p.w + tw0;
            } else {
                // one full bucket compute (d0), then a single threshold test for d3:
                // d3 <= d0, so bucket(d3)==bucket(d0) iff d3 >= T_{b0}.
                const int d0 = max(tsn - tsd[v].x, 1);
                const int d3 = max(tsn - tsd[v].w, 1);
                const int4 q0 = s_lut[31 - __clz(d0)];
                const int b0 = q0.x + (d0 >= q0.y) + (d0 >= q0.z) + (d0 >= q0.w);
                if (d3 >= s_T[b0]) {
                    // bucket uniform across the chunk (common case)
                    const float w = s_tsw[b0];
                    rv.x = p.x + w;
                    rv.y = p.y + w;
                    rv.z = p.z + w;
                    rv.w = p.w + w;
                } else {
                    const int d1 = max(tsn - tsd[v].y, 1);
                    const int d2 = max(tsn - tsd[v].z, 1);
                    const int4 q1 = s_lut[31 - __clz(d1)];
                    const int4 q2 = s_lut[31 - __clz(d2)];
                    const int4 q3 = s_lut[31 - __clz(d3)];
                    const int b1 = q1.x + (d1 >= q1.y) + (d1 >= q1.z) + (d1 >= q1.w);
                    const int b2 = q2.x + (d2 >= q2.y) + (d2 >= q2.z) + (d2 >= q2.w);
                    const int b3 = q3.x + (d3 >= q3.y) + (d3 >= q3.z) + (d3 >= q3.w);
                    rv.x = p.x + s_tsw[b0];
                    rv.y = p.y + s_tsw[b1];
                    rv.z = p.z + s_tsw[b2];
                    rv.w = p.w + s_tsw[b3];
                }
            }
            *(float4*)(outrow + j0) = rv;            // coalesced STG.128
        }
    }
}

extern "C" void kernel_launch(void* const* d_in, const int* in_sizes, int n_in,
                              void* d_out, int out_size)
{
    const int*   ts    = (const int*)d_in[0];    // int32 [16,2048]
    const float* ts_w  = (const float*)d_in[1];  // [129]
    const float* pos_w = (const float*)d_in[2];  // [4095]
    float*       out   = (float*)d_out;          // [16,2048,2048] fp32

    dim3 grid(NN / RPB, BB);
    bias_kernel<<<grid, THREADS>>>(ts, ts_w, pos_w, out);
}

// round 14
// speedup vs baseline: 1.2516x; 1.0391x over previous
#include <cuda_runtime.h>
#include <cuda_bf16.h>

// Problem shape (fixed by the dataset): B=16, N=2048, NUM_BUCKETS=128
#define BB      16
#define NN      2048
#define NBUCK   128
#define THREADS 256
#define RPB     8                 // rows per block, i-stride 4 (same i mod 4)
#define VPT     2                 // float4 chunks per thread per row: 2048/(256*4)

// out[b,i,j] = pos_w[N-1 + j - i] + ts_w[bucket(b,i,j)]
// bucket = trunc( logf(max(|td|,1)) / 0.301f ), td = ts[min(i+1,N-1)] - ts[j] (j<=i), else 0.
// td < 1e7 -> max bucket 53. Integer form: bucket(d) = #{k>=1 : T_k <= d},
// T_k = min{d : logf((float)d)/0.301f >= k}; <=3 thresholds per octave ->
// bucket(d) = lut[e].base + (d>=t1)+(d>=t2)+(d>=t3), e = ilog2(d).
// ts sorted => within a 4-chunk d0>=d3, so bucket uniform over the chunk iff
// d3 >= T_{b0} (single threshold test instead of a second full bucket compute).
// R13 post-mortem: co-bound (issue 70 / L1 61 / DRAM 58) at occ 59% => latency
// limited. This round: occupancy 6->7 blocks, immediate-folded addressing,
// streaming stores. Arithmetic unchanged (rel_err bit-identical).
__global__ __launch_bounds__(THREADS, 7)   // cap 36 regs -> 7 blocks/SM (87.5%)
void bias_kernel(const int*   __restrict__ ts,      // int32 [B,N]
                 const float* __restrict__ ts_w,    // [129]
                 const float* __restrict__ pos_w,   // [2N-1]
                 float*       __restrict__ out)     // [B,N,N] fp32
{
    __shared__ __align__(16) float s_pos[2080];  // pos window for this block's 8 rows
    __shared__ int   s_T[64];                    // thresholds: T_0=1, T_1..T_53
    __shared__ int4  s_lut[24];                  // per-exponent {base, t1, t2, t3}
    __shared__ float s_tsw[NBUCK + 1];
    __shared__ int   s_tsn[RPB];

    const int t   = threadIdx.x;
    const int blk = blockIdx.x;                  // 0..255
    const int b   = blockIdx.y;
    // Rows: base + 4r, r=0..7.  base mod 4 constant within block.
    const int base = (blk & 3) + (blk >> 2) * 32;
    const int o7   = 2047 - base - 28;           // pos_w offset of staged window start
    const int* tsrow = ts + (size_t)b * NN;

    // ---- stage pos window (2076 floats), coalesced ----
    #pragma unroll
    for (int x = t; x < 2076; x += THREADS)
        s_pos[x] = pos_w[o7 + x];

    // ---- thresholds: exact match of precise logf(x)/0.301f bucketization ----
    if (t <= 53) {
        if (t == 0) {
            s_T[0] = 1;
        } else {
            const float k = (float)t;
            int d = (int)ceilf(expf(0.301f * k));
            if (d < 2) d = 2;
            #pragma unroll 1
            while (d > 2 && (logf((float)(d - 1)) / 0.301f) >= k) d--;
            #pragma unroll 1
            while ((logf((float)d) / 0.301f) < k) d++;
            s_T[t] = d;
        }
    }
    if (t >= 54 && t < 64) s_T[t] = 0x7FFFFFFF;  // sentinel
    if (t <= NBUCK) s_tsw[t] = ts_w[t];
    if (t < RPB) {
        int i = base + 4 * t;
        s_tsn[t] = tsrow[(i < NN - 1) ? (i + 1) : (NN - 1)];
    }

    // Register-cache this thread's 8 timestamps as int4 (4 consecutive j per chunk).
    int4 tsd[VPT];
    const int4* tsrow4 = (const int4*)tsrow;
    #pragma unroll
    for (int v = 0; v < VPT; v++)
        tsd[v] = tsrow4[t + v * THREADS];

    __syncthreads();

    if (t < 24) {
        const int lo = 1 << t;
        int cnt = 0;
        #pragma unroll
        for (int k = 1; k <= 53; k++) cnt += (s_T[k] <= lo) ? 1 : 0;
        int4 q;
        q.x = cnt;
        q.y = (cnt + 1 <= 53) ? s_T[cnt + 1] : 0x7FFFFFFF;
        q.z = (cnt + 2 <= 53) ? s_T[cnt + 2] : 0x7FFFFFFF;
        q.w = (cnt + 3 <= 53) ? s_T[cnt + 3] : 0x7FFFFFFF;
        s_lut[t] = q;
    }
    __syncthreads();

    const float tw0 = s_tsw[0];
    // Single 64-bit base; all row/chunk offsets become compile-time immediates.
    float* const outb = out + ((size_t)b * NN + base) * (size_t)NN;

    #pragma unroll
    for (int v = 0; v < VPT; v++) {
        const int j0 = 4 * (t + v * THREADS);        // warp: 128 consecutive j
        float* const op = outb + j0;                  // row stores at op + r*4*NN (imm)
        const float* const pp = &s_pos[28 + j0];      // row loads at pp - 4*r (imm)
        const int4 td = tsd[v];

        #pragma unroll
        for (int r = 0; r < RPB; r++) {
            const int i   = base + 4 * r;
            const int tsn = s_tsn[r];
            const float4 p = *(const float4*)(pp - 4 * r);   // aligned LDS.128

            float4 rv;
            if (j0 > i) {
                // strictly upper triangle: bucket 0
                rv.x = p.x + tw0;
                rv.y = p.y + tw0;
                rv.z = p.z + tw0;
                rv.w = p.w + tw0;
            } else {
                // one full bucket compute (d0), then a single threshold test for d3:
                // d3 <= d0, so bucket(d3)==bucket(d0) iff d3 >= T_{b0}.
                const int d0 = max(tsn - td.x, 1);
                const int d3 = max(tsn - td.w, 1);
                const int4 q0 = s_lut[31 - __clz(d0)];
                const int b0 = q0.x + (d0 >= q0.y) + (d0 >= q0.z) + (d0 >= q0.w);
                if (d3 >= s_T[b0]) {
                    // bucket uniform across the chunk (common case)
                    const float w = s_tsw[b0];
                    rv.x = p.x + w;
                    rv.y = p.y + w;
                    rv.z = p.z + w;
                    rv.w = p.w + w;
                } else {
                    const int d1 = max(tsn - td.y, 1);
                    const int d2 = max(tsn - td.z, 1);
                    const int4 q1 = s_lut[31 - __clz(d1)];
                    const int4 q2 = s_lut[31 - __clz(d2)];
                    const int4 q3 = s_lut[31 - __clz(d3)];
                    const int b1 = q1.x + (d1 >= q1.y) + (d1 >= q1.z) + (d1 >= q1.w);
                    const int b2 = q2.x + (d2 >= q2.y) + (d2 >= q2.z) + (d2 >= q2.w);
                    const int b3 = q3.x + (d3 >= q3.y) + (d3 >= q3.z) + (d3 >= q3.w);
                    rv.x = p.x + s_tsw[b0];
                    rv.y = p.y + s_tsw[b1];
                    rv.z = p.z + s_tsw[b2];
                    rv.w = p.w + s_tsw[b3];
                }
            }
            // streaming store (write-once data, evict-first), coalesced STG.128
            __stcs((float4*)(op + r * 4 * NN), rv);
        }
    }
}

extern "C" void kernel_launch(void* const* d_in, const int* in_sizes, int n_in,
                              void* d_out, int out_size)
{
    const int*   ts    = (const int*)d_in[0];    // int32 [16,2048]
    const float* ts_w  = (const float*)d_in[1];  // [129]
    const float* pos_w = (const float*)d_in[2];  // [4095]
    float*       out   = (float*)d_out;          // [16,2048,2048] fp32

    dim3 grid(NN / RPB, BB);
    bias_kernel<<<grid, THREADS>>>(ts, ts_w, pos_w, out);
}